// round 8
// baseline (speedup 1.0000x reference)
#include <cuda_runtime.h>
#include <cuda_fp16.h>
#include <stdint.h>
#include <math.h>

#define D_IN     32
#define KF       832            // padded feature dim (13*64)
#define DIM      512
#define D_OUT    10
#define NX       1024
#define NC       100000
#define NCPAD    102400         // 800 * 128
#define NROWS    (NCPAD + NX)   // 103424 = 808*128
#define NSPLIT   800            // candidate blocks of 128
#define TWO_PI   6.283185307179586f

// stage geometry: K-chunk 64 halves (128B) per tile row, 144B padded stride
#define ROWSTR   144
#define TILEB    (128 * ROWSTR)     // 18432
#define STAGEB   (2 * TILEB)        // 36864 (A + B)
#define NSTAGE   3
#define DYNSMEM  (NSTAGE * STAGEB)  // 110592

// ---------------- device scratch (alloc-free) ----------------
__device__ __align__(16) __half g_fb[(size_t)NROWS * KF];   // fp16 feats
__device__ __align__(16) __half g_wb[(size_t)DIM * KF];     // fp16 enc_w
__device__ __align__(16) __half g_emb[(size_t)NROWS * DIM]; // fp16 embeddings
__device__ float g_nrm4[(size_t)NROWS * 4];                 // per-128col partial norms
__device__ float g_nrm[NROWS];
__device__ float g_part[(size_t)NX * NSPLIT * D_OUT];

// ---------------- PTX helpers (base-sm_103 legal) ----------------
__device__ __forceinline__ uint32_t smem_u32(const void* p) {
    uint32_t a;
    asm("{ .reg .u64 t; cvta.to.shared.u64 t, %1; cvt.u32.u64 %0, t; }" : "=r"(a) : "l"(p));
    return a;
}
__device__ __forceinline__ void ldsm4(uint32_t& r0, uint32_t& r1, uint32_t& r2, uint32_t& r3, uint32_t a) {
    asm volatile("ldmatrix.sync.aligned.m8n8.x4.shared.b16 {%0,%1,%2,%3}, [%4];"
                 : "=r"(r0), "=r"(r1), "=r"(r2), "=r"(r3) : "r"(a));
}
__device__ __forceinline__ void mma16816(float* c, const uint32_t* a, const uint32_t* b) {
    asm volatile("mma.sync.aligned.m16n8k16.row.col.f32.f16.f16.f32 "
                 "{%0,%1,%2,%3}, {%4,%5,%6,%7}, {%8,%9}, {%0,%1,%2,%3};"
                 : "+f"(c[0]), "+f"(c[1]), "+f"(c[2]), "+f"(c[3])
                 : "r"(a[0]), "r"(a[1]), "r"(a[2]), "r"(a[3]), "r"(b[0]), "r"(b[1]));
}
__device__ __forceinline__ void cp16(uint32_t dst, const void* src) {
    asm volatile("cp.async.ca.shared.global [%0], [%1], 16;" :: "r"(dst), "l"(src));
}
#define CP_COMMIT() asm volatile("cp.async.commit_group;" ::: "memory")
#define CP_WAIT1()  asm volatile("cp.async.wait_group 1;" ::: "memory")

__device__ __forceinline__ uint32_t h2pack(float a, float b) {
    __half2 h = __floats2half2_rn(a, b);
    return *(uint32_t*)&h;
}

// fast sincos on the FMA pipe: quadrant reduction via magic-number rounding,
// Taylor deg-9/8 on [-pi/4, pi/4] (abs err < 3e-8). Robust for |z| < 2^22.
__device__ __forceinline__ void fsincos(float z, float* s, float* c) {
    const float t  = z * 0.6366197723675814f;
    const float qm = t + 12582912.0f;
    const float q  = qm - 12582912.0f;
    const int   iq = (int)__float_as_uint(qm) & 3;
    float r = fmaf(q, -1.57079637e+00f, z);
    r = fmaf(q, 4.3711388e-08f, r);
    const float r2 = r * r;
    float ps = fmaf(r2, fmaf(r2, fmaf(r2, fmaf(r2, 2.7557319e-6f, -1.9841270e-4f),
                    8.3333333e-3f), -1.6666667e-1f), 1.0f) * r;
    float pc = fmaf(r2, fmaf(r2, fmaf(r2, fmaf(r2, 2.4801587e-5f, -1.3888889e-3f),
                    4.1666667e-2f), -5.0e-1f), 1.0f);
    float ss = (iq & 1) ? pc : ps;
    float cc = (iq & 1) ? ps : pc;
    if (iq & 2) ss = -ss;
    if ((iq + 1) & 2) cc = -cc;
    *s = ss; *c = cc;
}

// stage one 128-row x 128-byte chunk for A and B: 2048 cp16 / 256 thr = 8 each
__device__ __forceinline__ void stageAB(uint32_t sbase, const char* gA, const char* gB,
                                        int strA, int strB, int tid)
{
#pragma unroll
    for (int it = 0; it < 8; it++) {
        const int e   = it * 256 + tid;
        const int isB = e >> 10;
        const int id  = e & 1023;
        const int r   = id >> 3;
        const int s   = id & 7;
        const char* g = isB ? gB : gA;
        const int str = isB ? strB : strA;
        cp16(sbase + isB * TILEB + r * ROWSTR + s * 16, g + (size_t)r * str + s * 16);
    }
}

// warp microkernel: m16 x n128 over one 64-wide K chunk (4 x k16)
__device__ __forceinline__ void gemm_step(uint32_t sbuf, float (*acc)[4], int wid, int lane)
{
    const uint32_t aoff = sbuf + (uint32_t)(wid * 16 + (lane & 15)) * ROWSTR
                        + ((uint32_t)(lane >> 4) & 1) * 16;
    const uint32_t boff = sbuf + TILEB
                        + (uint32_t)((lane & 7) + ((lane >> 4) << 3)) * ROWSTR
                        + ((uint32_t)(lane >> 3) & 1) * 16;
#pragma unroll
    for (int ks = 0; ks < 4; ks++) {
        const uint32_t kc = ks * 32;
        uint32_t ah[4];
        ldsm4(ah[0], ah[1], ah[2], ah[3], aoff + kc);
        uint32_t bh[32];
#pragma unroll
        for (int p = 0; p < 8; p++)
            ldsm4(bh[4*p], bh[4*p+1], bh[4*p+2], bh[4*p+3], boff + kc + p * (16 * ROWSTR));
#pragma unroll
        for (int t = 0; t < 16; t++) mma16816(acc[t], ah, &bh[2*t]);
    }
}

// 3-stage single-sync pipelined GEMM mainloop
__device__ __forceinline__ void gemm_main(uint32_t sb, const char* gA, const char* gB,
                                          int str, int niter, float (*acc)[4],
                                          int wid, int lane, int tid)
{
    stageAB(sb, gA, gB, str, str, tid); CP_COMMIT();
    stageAB(sb + STAGEB, gA + 128, gB + 128, str, str, tid); CP_COMMIT();
    uint32_t bufs[3] = { sb, sb + STAGEB, sb + 2 * STAGEB };
    for (int kb = 0; kb < niter; kb++) {
        CP_WAIT1();
        __syncthreads();
        if (kb + 2 < niter)
            stageAB(bufs[(kb + 2) % 3], gA + (kb + 2) * 128, gB + (kb + 2) * 128, str, str, tid);
        CP_COMMIT();
        gemm_step(bufs[kb % 3], acc, wid, lane);
    }
}

// =====================================================================
// Kernel 1: feature generation -> fp16 feature rows (HFMA2 MLP)
// =====================================================================
__global__ void __launch_bounds__(256)
featgen_kernel(const float* __restrict__ cx, const float* __restrict__ xx,
               const float* __restrict__ freq, const float* __restrict__ plr_w,
               const float* __restrict__ plr_b)
{
    __shared__ float    s_x[256 * 33];
    __shared__ float    s_fr[384];
    __shared__ uint32_t s_pw2[512];   // half2(w[2e][f], w[2e+1][f])
    __shared__ uint32_t s_pb2[16];
    const int tid = threadIdx.x;
    const size_t rowBase = (size_t)blockIdx.x * 256;

    for (int i = tid; i < 384; i += 256) s_fr[i] = TWO_PI * freq[i];
    for (int i = tid; i < 512; i += 256) {
        const int e2 = i >> 5, f = i & 31;
        s_pw2[i] = h2pack(plr_w[(2 * e2) * 32 + f], plr_w[(2 * e2 + 1) * 32 + f]);
    }
    if (tid < 16) s_pb2[tid] = h2pack(plr_b[2 * tid], plr_b[2 * tid + 1]);
    for (int i = tid; i < 256 * 32; i += 256) {
        const int r = i >> 5, k = i & 31;
        const size_t gr = rowBase + r;
        float v = 0.f;
        if (gr < NC) v = cx[gr * D_IN + k];
        else if (gr >= NCPAD) v = xx[(gr - NCPAD) * D_IN + k];
        s_x[r * 33 + k] = v;
    }
    __syncthreads();

    const float* xs = s_x + tid * 33;
    __half* dst = g_fb + (rowBase + tid) * KF;
    const __half2 zero2 = __float2half2_rn(0.f);

    for (int n = 0; n < 24; n++) {
        const float v = xs[n];
        __half2 hc[16], hs[16];
#pragma unroll
        for (int f = 0; f < 16; f++) {
            float ss, cc;
            fsincos(s_fr[n * 16 + f] * v, &ss, &cc);
            hs[f] = __float2half2_rn(ss);
            hc[f] = __float2half2_rn(cc);
        }
        uint32_t W[16];
#pragma unroll 4
        for (int e2 = 0; e2 < 16; e2++) {
            __half2 acc2 = *(const __half2*)&s_pb2[e2];
            const __half2* pw = (const __half2*)&s_pw2[e2 * 32];
#pragma unroll
            for (int f = 0; f < 16; f++) {
                acc2 = __hfma2(hc[f], pw[f], acc2);
                acc2 = __hfma2(hs[f], pw[16 + f], acc2);
            }
            const __half2 r2 = __hmax2(acc2, zero2);
            W[e2] = *(const uint32_t*)&r2;
        }
        uint4* dq = (uint4*)((char*)dst + n * 64);
#pragma unroll
        for (int q = 0; q < 4; q++)
            dq[q] = make_uint4(W[4*q], W[4*q+1], W[4*q+2], W[4*q+3]);
    }
#pragma unroll 8
    for (int k = 0; k < 64; k++)   // cat tail 768..775 + zero pad to 832
        dst[768 + k] = __float2half_rn((k < 8) ? xs[24 + k] : 0.f);
}

// =====================================================================
// Kernel 2: pack enc_w -> fp16
// =====================================================================
__global__ void wprep_kernel(const float* __restrict__ enc_w)
{
    const int idx = blockIdx.x * 256 + threadIdx.x;
    if (idx >= DIM * KF) return;
    const int n = idx / KF, k = idx % KF;
    g_wb[(size_t)n * KF + k] = __float2half_rn((k < 776) ? enc_w[n * 776 + k] : 0.f);
}

// =====================================================================
// Kernel 3: encode GEMM (128 rows x 128 cols), fused partial norms
// =====================================================================
__global__ void __launch_bounds__(256)
enc_mma_kernel(const float* __restrict__ enc_b)
{
    extern __shared__ char sm[];
    __shared__ float s_bias[128];
    const uint32_t sb = smem_u32(sm);
    const int tid = threadIdx.x, wid = tid >> 5, lane = tid & 31;
    const size_t rowBase = (size_t)blockIdx.x * 128;
    const int colBase = blockIdx.y * 128;
    if (tid < 128) s_bias[tid] = enc_b[colBase + tid];

    const char* gA = (const char*)(g_fb + rowBase * KF);
    const char* gB = (const char*)(g_wb + (size_t)colBase * KF);

    float acc[16][4];
#pragma unroll
    for (int t = 0; t < 16; t++)
#pragma unroll
        for (int u = 0; u < 4; u++) acc[t][u] = 0.f;

    gemm_main(sb, gA, gB, KF * 2, 13, acc, wid, lane, tid);

    // epilogue: bias, fp16 store, quad-reduced partial norms
    const int g = lane >> 2, tig = lane & 3;
    const size_t r0 = rowBase + wid * 16 + g;
    const size_t r1 = r0 + 8;
    float n0 = 0.f, n1 = 0.f;
#pragma unroll
    for (int nt = 0; nt < 16; nt++) {
        const int col = nt * 8 + tig * 2;
        const float b0 = s_bias[col], b1 = s_bias[col + 1];
        const float v00 = acc[nt][0] + b0, v01 = acc[nt][1] + b1;
        const float v10 = acc[nt][2] + b0, v11 = acc[nt][3] + b1;
        *(uint32_t*)(g_emb + r0 * DIM + colBase + col) = h2pack(v00, v01);
        *(uint32_t*)(g_emb + r1 * DIM + colBase + col) = h2pack(v10, v11);
        n0 = fmaf(v00, v00, fmaf(v01, v01, n0));
        n1 = fmaf(v10, v10, fmaf(v11, v11, n1));
    }
    n0 += __shfl_xor_sync(0xffffffffu, n0, 1);
    n0 += __shfl_xor_sync(0xffffffffu, n0, 2);
    n1 += __shfl_xor_sync(0xffffffffu, n1, 1);
    n1 += __shfl_xor_sync(0xffffffffu, n1, 2);
    if (tig == 0) {
        g_nrm4[r0 * 4 + blockIdx.y] = n0;
        g_nrm4[r1 * 4 + blockIdx.y] = n1;
    }
}

// =====================================================================
// Kernel 4: sum partial norms; poison padded candidate rows (exp -> 0)
// =====================================================================
__global__ void __launch_bounds__(256)
norm4_kernel()
{
    const int row = blockIdx.x * 256 + threadIdx.x;
    if (row >= NROWS) return;
    const float4 p = *(const float4*)(g_nrm4 + (size_t)row * 4);
    const float s = (p.x + p.y) + (p.z + p.w);
    g_nrm[row] = (row < NC || row >= NCPAD) ? s : 1e30f;
}

// =====================================================================
// Kernel 5: NCA GEMM + distance/exp/class partials
// =====================================================================
__global__ void __launch_bounds__(256)
nca_mma_kernel(const int* __restrict__ cy)
{
    extern __shared__ char sm[];
    __shared__ float s_cn[128];
    __shared__ int   s_cy[128];
    const uint32_t sb = smem_u32(sm);
    const int tid = threadIdx.x, wid = tid >> 5, lane = tid & 31;
    const int xBase = blockIdx.x * 128;
    const int cBase = blockIdx.y * 128;

    if (tid < 128) {
        const int j = cBase + tid;
        s_cn[tid] = g_nrm[j];                 // 1e30 for padded -> exp == 0
        s_cy[tid] = cy[min(j, NC - 1)];
    }

    const char* gA = (const char*)(g_emb + (size_t)(NCPAD + xBase) * DIM);
    const char* gB = (const char*)(g_emb + (size_t)cBase * DIM);

    float acc[16][4];
#pragma unroll
    for (int t = 0; t < 16; t++)
#pragma unroll
        for (int u = 0; u < 4; u++) acc[t][u] = 0.f;

    gemm_main(sb, gA, gB, DIM * 2, 8, acc, wid, lane, tid);

    // epilogue: distances -> exp -> class partials (scores <= 0, no max needed)
    const int g = lane >> 2, tig = lane & 3;
    const int xr0 = xBase + wid * 16 + g;
    const float xn0 = g_nrm[NCPAD + xr0];
    const float xn1 = g_nrm[NCPAD + xr0 + 8];
    float n0[D_OUT], n1[D_OUT];
#pragma unroll
    for (int c = 0; c < D_OUT; c++) { n0[c] = 0.f; n1[c] = 0.f; }

#pragma unroll
    for (int nt = 0; nt < 16; nt++) {
#pragma unroll
        for (int u = 0; u < 2; u++) {
            const int col = nt * 8 + tig * 2 + u;
            const float cn = s_cn[col];
            const int   y  = s_cy[col];
            const float sq0 = fmaxf(xn0 + cn - 2.f * acc[nt][u],     1e-12f);
            const float sq1 = fmaxf(xn1 + cn - 2.f * acc[nt][2 + u], 1e-12f);
            const float e0 = __expf(-sqrtf(sq0));
            const float e1 = __expf(-sqrtf(sq1));
#pragma unroll
            for (int c = 0; c < D_OUT; c++) {
                n0[c] += (y == c) ? e0 : 0.f;
                n1[c] += (y == c) ? e1 : 0.f;
            }
        }
    }
#pragma unroll
    for (int c = 0; c < D_OUT; c++) {
        n0[c] += __shfl_xor_sync(0xffffffffu, n0[c], 1);
        n0[c] += __shfl_xor_sync(0xffffffffu, n0[c], 2);
        n1[c] += __shfl_xor_sync(0xffffffffu, n1[c], 1);
        n1[c] += __shfl_xor_sync(0xffffffffu, n1[c], 2);
    }
    if (tig == 0) {
        float* P0 = g_part + ((size_t)xr0 * NSPLIT + blockIdx.y) * D_OUT;
        float* P1 = g_part + ((size_t)(xr0 + 8) * NSPLIT + blockIdx.y) * D_OUT;
#pragma unroll
        for (int c = 0; c < D_OUT; c++) { P0[c] = n0[c]; P1[c] = n1[c]; }
    }
}

// =====================================================================
// Kernel 6: reduce partials -> log-probs (warp per x row, deterministic)
// =====================================================================
__global__ void __launch_bounds__(256)
finalize_kernel(float* __restrict__ out)
{
    const int w = (blockIdx.x * 256 + threadIdx.x) >> 5;
    const int lane = threadIdx.x & 31;
    if (w >= NX) return;
    const float* P = g_part + (size_t)w * NSPLIT * D_OUT;
    float n[D_OUT];
#pragma unroll
    for (int c = 0; c < D_OUT; c++) n[c] = 0.f;
    for (int s = lane; s < NSPLIT; s += 32) {
        const float* q = P + s * D_OUT;
#pragma unroll
        for (int c = 0; c < D_OUT; c++) n[c] += q[c];
    }
#pragma unroll
    for (int o = 16; o; o >>= 1)
#pragma unroll
        for (int c = 0; c < D_OUT; c++) n[c] += __shfl_xor_sync(0xffffffffu, n[c], o);
    if (lane == 0) {
        float l = 0.f;
#pragma unroll
        for (int c = 0; c < D_OUT; c++) l += n[c];
        const float inv = 1.0f / l;
#pragma unroll
        for (int c = 0; c < D_OUT; c++)
            out[w * D_OUT + c] = logf(n[c] * inv + 1e-7f);
    }
}

// =====================================================================
extern "C" void kernel_launch(void* const* d_in, const int* in_sizes, int n_in,
                              void* d_out, int out_size)
{
    const float* x     = (const float*)d_in[0];
    const float* cx    = (const float*)d_in[1];
    const int*   cy    = (const int*)d_in[2];
    const float* freq  = (const float*)d_in[3];
    const float* plr_w = (const float*)d_in[4];
    const float* plr_b = (const float*)d_in[5];
    const float* enc_w = (const float*)d_in[6];
    const float* enc_b = (const float*)d_in[7];
    float* out = (float*)d_out;

    cudaFuncSetAttribute(enc_mma_kernel, cudaFuncAttributeMaxDynamicSharedMemorySize, DYNSMEM);
    cudaFuncSetAttribute(nca_mma_kernel, cudaFuncAttributeMaxDynamicSharedMemorySize, DYNSMEM);

    featgen_kernel<<<NROWS / 256, 256>>>(cx, x, freq, plr_w, plr_b);
    wprep_kernel<<<(DIM * KF + 255) / 256, 256>>>(enc_w);
    enc_mma_kernel<<<dim3(NROWS / 128, DIM / 128), 256, DYNSMEM>>>(enc_b);
    norm4_kernel<<<(NROWS + 255) / 256, 256>>>();
    nca_mma_kernel<<<dim3(NX / 128, NCPAD / 128), 256, DYNSMEM>>>(cy);
    finalize_kernel<<<(NX * 32) / 256, 256>>>(out);
}

// round 9
// speedup vs baseline: 1.1740x; 1.1740x over previous
#include <cuda_runtime.h>
#include <cuda_fp16.h>
#include <stdint.h>
#include <math.h>

#define D_IN     32
#define KF       832            // padded feature dim (26*32)
#define DIM      512
#define D_OUT    10
#define NX       1024
#define NC       100000
#define NCPAD    102400         // 800 * 128
#define NROWS    (NCPAD + NX)   // 103424 = 808*128
#define NSPLIT   800            // candidate blocks of 128
#define TWO_PI   6.283185307179586f

// stage geometry: K-chunk 32 halves (64B) per tile row, 80B padded stride
#define ROWSTR   80
#define TILEB    (128 * ROWSTR)     // 10240
#define STAGEB   (2 * TILEB)        // 20480 (A + B)
#define NSTAGE   3
#define DYNSMEM  (NSTAGE * STAGEB)  // 61440 -> 2 CTAs/SM by smem

// ---------------- device scratch (alloc-free) ----------------
__device__ __align__(16) __half g_fb[(size_t)NROWS * KF];   // fp16 feats
__device__ __align__(16) __half g_wb[(size_t)DIM * KF];     // fp16 enc_w
__device__ __align__(16) __half g_emb[(size_t)NROWS * DIM]; // fp16 embeddings
__device__ float g_nrm4[(size_t)NROWS * 4];                 // per-128col partial norms
__device__ float g_nrm[NROWS];
__device__ float g_part[(size_t)NX * NSPLIT * D_OUT];

// ---------------- PTX helpers (base-sm_103 legal) ----------------
__device__ __forceinline__ uint32_t smem_u32(const void* p) {
    uint32_t a;
    asm("{ .reg .u64 t; cvta.to.shared.u64 t, %1; cvt.u32.u64 %0, t; }" : "=r"(a) : "l"(p));
    return a;
}
__device__ __forceinline__ void ldsm4(uint32_t& r0, uint32_t& r1, uint32_t& r2, uint32_t& r3, uint32_t a) {
    asm volatile("ldmatrix.sync.aligned.m8n8.x4.shared.b16 {%0,%1,%2,%3}, [%4];"
                 : "=r"(r0), "=r"(r1), "=r"(r2), "=r"(r3) : "r"(a));
}
__device__ __forceinline__ void mma16816(float* c, const uint32_t* a, const uint32_t* b) {
    asm volatile("mma.sync.aligned.m16n8k16.row.col.f32.f16.f16.f32 "
                 "{%0,%1,%2,%3}, {%4,%5,%6,%7}, {%8,%9}, {%0,%1,%2,%3};"
                 : "+f"(c[0]), "+f"(c[1]), "+f"(c[2]), "+f"(c[3])
                 : "r"(a[0]), "r"(a[1]), "r"(a[2]), "r"(a[3]), "r"(b[0]), "r"(b[1]));
}
__device__ __forceinline__ void cp16(uint32_t dst, const void* src) {
    asm volatile("cp.async.ca.shared.global [%0], [%1], 16;" :: "r"(dst), "l"(src));
}
#define CP_COMMIT() asm volatile("cp.async.commit_group;" ::: "memory")
#define CP_WAIT1()  asm volatile("cp.async.wait_group 1;" ::: "memory")

__device__ __forceinline__ uint32_t h2pack(float a, float b) {
    __half2 h = __floats2half2_rn(a, b);
    return *(uint32_t*)&h;
}

// fast sincos on the FMA pipe: quadrant reduction via magic-number rounding,
// Taylor deg-9/8 on [-pi/4, pi/4] (abs err < 3e-8). Robust for |z| < 2^22.
__device__ __forceinline__ void fsincos(float z, float* s, float* c) {
    const float t  = z * 0.6366197723675814f;
    const float qm = t + 12582912.0f;
    const float q  = qm - 12582912.0f;
    const int   iq = (int)__float_as_uint(qm) & 3;
    float r = fmaf(q, -1.57079637e+00f, z);
    r = fmaf(q, 4.3711388e-08f, r);
    const float r2 = r * r;
    float ps = fmaf(r2, fmaf(r2, fmaf(r2, fmaf(r2, 2.7557319e-6f, -1.9841270e-4f),
                    8.3333333e-3f), -1.6666667e-1f), 1.0f) * r;
    float pc = fmaf(r2, fmaf(r2, fmaf(r2, fmaf(r2, 2.4801587e-5f, -1.3888889e-3f),
                    4.1666667e-2f), -5.0e-1f), 1.0f);
    float ss = (iq & 1) ? pc : ps;
    float cc = (iq & 1) ? ps : pc;
    if (iq & 2) ss = -ss;
    if ((iq + 1) & 2) cc = -cc;
    *s = ss; *c = cc;
}

// stage one 128-row x 64-byte chunk for A and B: 1024 cp16 / 256 thr = 4 each
__device__ __forceinline__ void stageAB(uint32_t sbase, const char* gA, const char* gB,
                                        int str, int tid)
{
#pragma unroll
    for (int it = 0; it < 4; it++) {
        const int e   = it * 256 + tid;
        const int isB = e >> 9;
        const int id  = e & 511;
        const int r   = id >> 2;
        const int s   = id & 3;
        const char* g = isB ? gB : gA;
        cp16(sbase + isB * TILEB + r * ROWSTR + s * 16, g + (size_t)r * str + s * 16);
    }
}

// warp microkernel: m16 x n128 over one 32-wide K chunk (2 x k16)
__device__ __forceinline__ void gemm_step(uint32_t sbuf, float (*acc)[4], int wid, int lane)
{
    const uint32_t aoff = sbuf + (uint32_t)(wid * 16 + (lane & 15)) * ROWSTR
                        + ((uint32_t)(lane >> 4) & 1) * 16;
    const uint32_t boff = sbuf + TILEB
                        + (uint32_t)((lane & 7) + ((lane >> 4) << 3)) * ROWSTR
                        + ((uint32_t)(lane >> 3) & 1) * 16;
#pragma unroll
    for (int ks = 0; ks < 2; ks++) {
        const uint32_t kc = ks * 32;
        uint32_t ah[4];
        ldsm4(ah[0], ah[1], ah[2], ah[3], aoff + kc);
        uint32_t bh[32];
#pragma unroll
        for (int p = 0; p < 8; p++)
            ldsm4(bh[4*p], bh[4*p+1], bh[4*p+2], bh[4*p+3], boff + kc + p * (16 * ROWSTR));
#pragma unroll
        for (int t = 0; t < 16; t++) mma16816(acc[t], ah, &bh[2*t]);
    }
}

// 3-stage, single-sync pipelined GEMM mainloop (K advances 64B per iter)
__device__ __forceinline__ void gemm_main(uint32_t sb, const char* gA, const char* gB,
                                          int str, int niter, float (*acc)[4],
                                          int wid, int lane, int tid)
{
    stageAB(sb, gA, gB, str, tid); CP_COMMIT();
    stageAB(sb + STAGEB, gA + 64, gB + 64, str, tid); CP_COMMIT();
    uint32_t bufs[3] = { sb, sb + STAGEB, sb + 2 * STAGEB };
    for (int kb = 0; kb < niter; kb++) {
        CP_WAIT1();
        __syncthreads();
        if (kb + 2 < niter)
            stageAB(bufs[(kb + 2) % 3], gA + (kb + 2) * 64, gB + (kb + 2) * 64, str, tid);
        CP_COMMIT();
        gemm_step(bufs[kb % 3], acc, wid, lane);
    }
}

// =====================================================================
// Kernel 1: feature generation -> fp16 feature rows (HFMA2 MLP)
// =====================================================================
__global__ void __launch_bounds__(256)
featgen_kernel(const float* __restrict__ cx, const float* __restrict__ xx,
               const float* __restrict__ freq, const float* __restrict__ plr_w,
               const float* __restrict__ plr_b)
{
    __shared__ float    s_x[256 * 33];
    __shared__ float    s_fr[384];
    __shared__ uint32_t s_pw2[512];   // half2(w[2e][f], w[2e+1][f])
    __shared__ uint32_t s_pb2[16];
    const int tid = threadIdx.x;
    const size_t rowBase = (size_t)blockIdx.x * 256;

    for (int i = tid; i < 384; i += 256) s_fr[i] = TWO_PI * freq[i];
    for (int i = tid; i < 512; i += 256) {
        const int e2 = i >> 5, f = i & 31;
        s_pw2[i] = h2pack(plr_w[(2 * e2) * 32 + f], plr_w[(2 * e2 + 1) * 32 + f]);
    }
    if (tid < 16) s_pb2[tid] = h2pack(plr_b[2 * tid], plr_b[2 * tid + 1]);
    for (int i = tid; i < 256 * 32; i += 256) {
        const int r = i >> 5, k = i & 31;
        const size_t gr = rowBase + r;
        float v = 0.f;
        if (gr < NC) v = cx[gr * D_IN + k];
        else if (gr >= NCPAD) v = xx[(gr - NCPAD) * D_IN + k];
        s_x[r * 33 + k] = v;
    }
    __syncthreads();

    const float* xs = s_x + tid * 33;
    __half* dst = g_fb + (rowBase + tid) * KF;
    const __half2 zero2 = __float2half2_rn(0.f);

    for (int n = 0; n < 24; n++) {
        const float v = xs[n];
        __half2 hc[16], hs[16];
#pragma unroll
        for (int f = 0; f < 16; f++) {
            float ss, cc;
            fsincos(s_fr[n * 16 + f] * v, &ss, &cc);
            hs[f] = __float2half2_rn(ss);
            hc[f] = __float2half2_rn(cc);
        }
        uint32_t W[16];
#pragma unroll 4
        for (int e2 = 0; e2 < 16; e2++) {
            __half2 acc2 = *(const __half2*)&s_pb2[e2];
            const __half2* pw = (const __half2*)&s_pw2[e2 * 32];
#pragma unroll
            for (int f = 0; f < 16; f++) {
                acc2 = __hfma2(hc[f], pw[f], acc2);
                acc2 = __hfma2(hs[f], pw[16 + f], acc2);
            }
            const __half2 r2 = __hmax2(acc2, zero2);
            W[e2] = *(const uint32_t*)&r2;
        }
        uint4* dq = (uint4*)((char*)dst + n * 64);
#pragma unroll
        for (int q = 0; q < 4; q++)
            dq[q] = make_uint4(W[4*q], W[4*q+1], W[4*q+2], W[4*q+3]);
    }
#pragma unroll 8
    for (int k = 0; k < 64; k++)   // cat tail 768..775 + zero pad to 832
        dst[768 + k] = __float2half_rn((k < 8) ? xs[24 + k] : 0.f);
}

// =====================================================================
// Kernel 2: pack enc_w -> fp16
// =====================================================================
__global__ void wprep_kernel(const float* __restrict__ enc_w)
{
    const int idx = blockIdx.x * 256 + threadIdx.x;
    if (idx >= DIM * KF) return;
    const int n = idx / KF, k = idx % KF;
    g_wb[(size_t)n * KF + k] = __float2half_rn((k < 776) ? enc_w[n * 776 + k] : 0.f);
}

// =====================================================================
// Kernel 3: encode GEMM (128 rows x 128 cols), fused partial norms
// =====================================================================
__global__ void __launch_bounds__(256, 2)
enc_mma_kernel(const float* __restrict__ enc_b)
{
    extern __shared__ char sm[];
    __shared__ float s_bias[128];
    const uint32_t sb = smem_u32(sm);
    const int tid = threadIdx.x, wid = tid >> 5, lane = tid & 31;
    const size_t rowBase = (size_t)blockIdx.x * 128;
    const int colBase = blockIdx.y * 128;
    if (tid < 128) s_bias[tid] = enc_b[colBase + tid];

    const char* gA = (const char*)(g_fb + rowBase * KF);
    const char* gB = (const char*)(g_wb + (size_t)colBase * KF);

    float acc[16][4];
#pragma unroll
    for (int t = 0; t < 16; t++)
#pragma unroll
        for (int u = 0; u < 4; u++) acc[t][u] = 0.f;

    gemm_main(sb, gA, gB, KF * 2, 26, acc, wid, lane, tid);

    // epilogue: bias, fp16 store, quad-reduced partial norms
    const int g = lane >> 2, tig = lane & 3;
    const size_t r0 = rowBase + wid * 16 + g;
    const size_t r1 = r0 + 8;
    float n0 = 0.f, n1 = 0.f;
#pragma unroll
    for (int nt = 0; nt < 16; nt++) {
        const int col = nt * 8 + tig * 2;
        const float b0 = s_bias[col], b1 = s_bias[col + 1];
        const float v00 = acc[nt][0] + b0, v01 = acc[nt][1] + b1;
        const float v10 = acc[nt][2] + b0, v11 = acc[nt][3] + b1;
        *(uint32_t*)(g_emb + r0 * DIM + colBase + col) = h2pack(v00, v01);
        *(uint32_t*)(g_emb + r1 * DIM + colBase + col) = h2pack(v10, v11);
        n0 = fmaf(v00, v00, fmaf(v01, v01, n0));
        n1 = fmaf(v10, v10, fmaf(v11, v11, n1));
    }
    n0 += __shfl_xor_sync(0xffffffffu, n0, 1);
    n0 += __shfl_xor_sync(0xffffffffu, n0, 2);
    n1 += __shfl_xor_sync(0xffffffffu, n1, 1);
    n1 += __shfl_xor_sync(0xffffffffu, n1, 2);
    if (tig == 0) {
        g_nrm4[r0 * 4 + blockIdx.y] = n0;
        g_nrm4[r1 * 4 + blockIdx.y] = n1;
    }
}

// =====================================================================
// Kernel 4: sum partial norms; poison padded candidate rows (exp -> 0)
// =====================================================================
__global__ void __launch_bounds__(256)
norm4_kernel()
{
    const int row = blockIdx.x * 256 + threadIdx.x;
    if (row >= NROWS) return;
    const float4 p = *(const float4*)(g_nrm4 + (size_t)row * 4);
    const float s = (p.x + p.y) + (p.z + p.w);
    g_nrm[row] = (row < NC || row >= NCPAD) ? s : 1e30f;
}

// =====================================================================
// Kernel 5: NCA GEMM + distance/exp/class partials
// =====================================================================
__global__ void __launch_bounds__(256, 2)
nca_mma_kernel(const int* __restrict__ cy)
{
    extern __shared__ char sm[];
    __shared__ float s_cn[128];
    __shared__ int   s_cy[128];
    const uint32_t sb = smem_u32(sm);
    const int tid = threadIdx.x, wid = tid >> 5, lane = tid & 31;
    const int xBase = blockIdx.x * 128;
    const int cBase = blockIdx.y * 128;

    if (tid < 128) {
        const int j = cBase + tid;
        s_cn[tid] = g_nrm[j];                 // 1e30 for padded -> exp == 0
        s_cy[tid] = cy[min(j, NC - 1)];
    }

    const char* gA = (const char*)(g_emb + (size_t)(NCPAD + xBase) * DIM);
    const char* gB = (const char*)(g_emb + (size_t)cBase * DIM);

    float acc[16][4];
#pragma unroll
    for (int t = 0; t < 16; t++)
#pragma unroll
        for (int u = 0; u < 4; u++) acc[t][u] = 0.f;

    gemm_main(sb, gA, gB, DIM * 2, 16, acc, wid, lane, tid);

    // epilogue: distances -> exp -> class partials (scores <= 0, no max needed)
    const int g = lane >> 2, tig = lane & 3;
    const int xr0 = xBase + wid * 16 + g;
    const float xn0 = g_nrm[NCPAD + xr0];
    const float xn1 = g_nrm[NCPAD + xr0 + 8];
    float n0[D_OUT], n1[D_OUT];
#pragma unroll
    for (int c = 0; c < D_OUT; c++) { n0[c] = 0.f; n1[c] = 0.f; }

#pragma unroll
    for (int nt = 0; nt < 16; nt++) {
#pragma unroll
        for (int u = 0; u < 2; u++) {
            const int col = nt * 8 + tig * 2 + u;
            const float cn = s_cn[col];
            const int   y  = s_cy[col];
            const float sq0 = fmaxf(xn0 + cn - 2.f * acc[nt][u],     1e-12f);
            const float sq1 = fmaxf(xn1 + cn - 2.f * acc[nt][2 + u], 1e-12f);
            const float e0 = __expf(-sqrtf(sq0));
            const float e1 = __expf(-sqrtf(sq1));
#pragma unroll
            for (int c = 0; c < D_OUT; c++) {
                n0[c] += (y == c) ? e0 : 0.f;
                n1[c] += (y == c) ? e1 : 0.f;
            }
        }
    }
#pragma unroll
    for (int c = 0; c < D_OUT; c++) {
        n0[c] += __shfl_xor_sync(0xffffffffu, n0[c], 1);
        n0[c] += __shfl_xor_sync(0xffffffffu, n0[c], 2);
        n1[c] += __shfl_xor_sync(0xffffffffu, n1[c], 1);
        n1[c] += __shfl_xor_sync(0xffffffffu, n1[c], 2);
    }
    if (tig == 0) {
        float* P0 = g_part + ((size_t)xr0 * NSPLIT + blockIdx.y) * D_OUT;
        float* P1 = g_part + ((size_t)(xr0 + 8) * NSPLIT + blockIdx.y) * D_OUT;
#pragma unroll
        for (int c = 0; c < D_OUT; c++) { P0[c] = n0[c]; P1[c] = n1[c]; }
    }
}

// =====================================================================
// Kernel 6: reduce partials -> log-probs (warp per x row, deterministic)
// =====================================================================
__global__ void __launch_bounds__(256)
finalize_kernel(float* __restrict__ out)
{
    const int w = (blockIdx.x * 256 + threadIdx.x) >> 5;
    const int lane = threadIdx.x & 31;
    if (w >= NX) return;
    const float* P = g_part + (size_t)w * NSPLIT * D_OUT;
    float n[D_OUT];
#pragma unroll
    for (int c = 0; c < D_OUT; c++) n[c] = 0.f;
    for (int s = lane; s < NSPLIT; s += 32) {
        const float* q = P + s * D_OUT;
#pragma unroll
        for (int c = 0; c < D_OUT; c++) n[c] += q[c];
    }
#pragma unroll
    for (int o = 16; o; o >>= 1)
#pragma unroll
        for (int c = 0; c < D_OUT; c++) n[c] += __shfl_xor_sync(0xffffffffu, n[c], o);
    if (lane == 0) {
        float l = 0.f;
#pragma unroll
        for (int c = 0; c < D_OUT; c++) l += n[c];
        const float inv = 1.0f / l;
#pragma unroll
        for (int c = 0; c < D_OUT; c++)
            out[w * D_OUT + c] = logf(n[c] * inv + 1e-7f);
    }
}

// =====================================================================
extern "C" void kernel_launch(void* const* d_in, const int* in_sizes, int n_in,
                              void* d_out, int out_size)
{
    const float* x     = (const float*)d_in[0];
    const float* cx    = (const float*)d_in[1];
    const int*   cy    = (const int*)d_in[2];
    const float* freq  = (const float*)d_in[3];
    const float* plr_w = (const float*)d_in[4];
    const float* plr_b = (const float*)d_in[5];
    const float* enc_w = (const float*)d_in[6];
    const float* enc_b = (const float*)d_in[7];
    float* out = (float*)d_out;

    cudaFuncSetAttribute(enc_mma_kernel, cudaFuncAttributeMaxDynamicSharedMemorySize, DYNSMEM);
    cudaFuncSetAttribute(nca_mma_kernel, cudaFuncAttributeMaxDynamicSharedMemorySize, DYNSMEM);

    featgen_kernel<<<NROWS / 256, 256>>>(cx, x, freq, plr_w, plr_b);
    wprep_kernel<<<(DIM * KF + 255) / 256, 256>>>(enc_w);
    enc_mma_kernel<<<dim3(NROWS / 128, DIM / 128), 256, DYNSMEM>>>(enc_b);
    norm4_kernel<<<(NROWS + 255) / 256, 256>>>();
    nca_mma_kernel<<<dim3(NX / 128, NCPAD / 128), 256, DYNSMEM>>>(cy);
    finalize_kernel<<<(NX * 32) / 256, 256>>>(out);
}

// round 10
// speedup vs baseline: 1.1800x; 1.0051x over previous
#include <cuda_runtime.h>
#include <cuda_fp16.h>
#include <stdint.h>
#include <math.h>

#define D_IN     32
#define KF       832            // padded feature dim (26*32)
#define DIM      512
#define D_OUT    10
#define NX       1024
#define NC       100000
#define NCPAD    102400         // 800 * 128
#define NROWS    (NCPAD + NX)   // 103424 = 808*128
#define NSPLIT   800            // candidate blocks of 128
#define NSPLIT2  (2 * NSPLIT)   // partial slots (x2 for n-warp split)
#define TWO_PI   6.283185307179586f

// stage geometry: K-chunk 32 halves (64B) per tile row, 80B padded stride
#define ROWSTR   80
#define TILEB    (128 * ROWSTR)     // 10240
#define STAGEB   (2 * TILEB)        // 20480 (A + B)
#define NSTAGE   3
#define DYNSMEM  (NSTAGE * STAGEB)  // 61440 -> 2 CTAs/SM by smem

// ---------------- device scratch (alloc-free) ----------------
__device__ __align__(16) __half g_fb[(size_t)NROWS * KF];   // fp16 feats
__device__ __align__(16) __half g_wb[(size_t)DIM * KF];     // fp16 enc_w
__device__ __align__(16) __half g_emb[(size_t)NROWS * DIM]; // fp16 embeddings
__device__ float g_nrm8[(size_t)NROWS * 8];                 // per-(128col x nwarp) partial norms
__device__ float g_nrm[NROWS];
__device__ float g_part[(size_t)NX * NSPLIT2 * D_OUT];

// ---------------- PTX helpers (base-sm_103 legal) ----------------
__device__ __forceinline__ uint32_t smem_u32(const void* p) {
    uint32_t a;
    asm("{ .reg .u64 t; cvta.to.shared.u64 t, %1; cvt.u32.u64 %0, t; }" : "=r"(a) : "l"(p));
    return a;
}
__device__ __forceinline__ void ldsm4(uint32_t& r0, uint32_t& r1, uint32_t& r2, uint32_t& r3, uint32_t a) {
    asm volatile("ldmatrix.sync.aligned.m8n8.x4.shared.b16 {%0,%1,%2,%3}, [%4];"
                 : "=r"(r0), "=r"(r1), "=r"(r2), "=r"(r3) : "r"(a));
}
__device__ __forceinline__ void mma16816(float* c, const uint32_t* a, const uint32_t* b) {
    asm volatile("mma.sync.aligned.m16n8k16.row.col.f32.f16.f16.f32 "
                 "{%0,%1,%2,%3}, {%4,%5,%6,%7}, {%8,%9}, {%0,%1,%2,%3};"
                 : "+f"(c[0]), "+f"(c[1]), "+f"(c[2]), "+f"(c[3])
                 : "r"(a[0]), "r"(a[1]), "r"(a[2]), "r"(a[3]), "r"(b[0]), "r"(b[1]));
}
__device__ __forceinline__ void cp16(uint32_t dst, const void* src) {
    asm volatile("cp.async.ca.shared.global [%0], [%1], 16;" :: "r"(dst), "l"(src));
}
#define CP_COMMIT() asm volatile("cp.async.commit_group;" ::: "memory")
#define CP_WAIT1()  asm volatile("cp.async.wait_group 1;" ::: "memory")

__device__ __forceinline__ uint32_t h2pack(float a, float b) {
    __half2 h = __floats2half2_rn(a, b);
    return *(uint32_t*)&h;
}

// fast sincos on the FMA pipe: quadrant reduction via magic-number rounding,
// Taylor deg-9/8 on [-pi/4, pi/4] (abs err < 3e-8). Robust for |z| < 2^22.
__device__ __forceinline__ void fsincos(float z, float* s, float* c) {
    const float t  = z * 0.6366197723675814f;
    const float qm = t + 12582912.0f;
    const float q  = qm - 12582912.0f;
    const int   iq = (int)__float_as_uint(qm) & 3;
    float r = fmaf(q, -1.57079637e+00f, z);
    r = fmaf(q, 4.3711388e-08f, r);
    const float r2 = r * r;
    float ps = fmaf(r2, fmaf(r2, fmaf(r2, fmaf(r2, 2.7557319e-6f, -1.9841270e-4f),
                    8.3333333e-3f), -1.6666667e-1f), 1.0f) * r;
    float pc = fmaf(r2, fmaf(r2, fmaf(r2, fmaf(r2, 2.4801587e-5f, -1.3888889e-3f),
                    4.1666667e-2f), -5.0e-1f), 1.0f);
    float ss = (iq & 1) ? pc : ps;
    float cc = (iq & 1) ? ps : pc;
    if (iq & 2) ss = -ss;
    if ((iq + 1) & 2) cc = -cc;
    *s = ss; *c = cc;
}

// stage one 128-row x 64-byte chunk for A and B: 1024 cp16 / 256 thr = 4 each
__device__ __forceinline__ void stageAB(uint32_t sbase, const char* gA, const char* gB,
                                        int str, int tid)
{
#pragma unroll
    for (int it = 0; it < 4; it++) {
        const int e   = it * 256 + tid;
        const int isB = e >> 9;
        const int id  = e & 511;
        const int r   = id >> 2;
        const int s   = id & 3;
        const char* g = isB ? gB : gA;
        cp16(sbase + isB * TILEB + r * ROWSTR + s * 16, g + (size_t)r * str + s * 16);
    }
}

// warp microkernel: m32 x n64 (4x2 warp grid) over one 32-wide K chunk
// acc[0..7] = m-frag0 (rows mw*32+0..15), acc[8..15] = m-frag1 (+16..31)
__device__ __forceinline__ void gemm_step(uint32_t sbuf, float (*acc)[4],
                                          int mw, int nw, int lane)
{
    const uint32_t a0 = sbuf + (uint32_t)(mw * 32 + (lane & 15)) * ROWSTR
                      + ((uint32_t)(lane >> 4) & 1) * 16;
    const uint32_t a1 = a0 + 16 * ROWSTR;
    const uint32_t b0 = sbuf + TILEB
                      + (uint32_t)(nw * 64 + (lane & 7) + ((lane >> 4) << 3)) * ROWSTR
                      + ((uint32_t)(lane >> 3) & 1) * 16;
#pragma unroll
    for (int ks = 0; ks < 2; ks++) {
        const uint32_t kc = ks * 32;
        uint32_t ah0[4], ah1[4];
        ldsm4(ah0[0], ah0[1], ah0[2], ah0[3], a0 + kc);
        ldsm4(ah1[0], ah1[1], ah1[2], ah1[3], a1 + kc);
        uint32_t bh[16];
#pragma unroll
        for (int p = 0; p < 4; p++)
            ldsm4(bh[4*p], bh[4*p+1], bh[4*p+2], bh[4*p+3], b0 + kc + p * (16 * ROWSTR));
#pragma unroll
        for (int t = 0; t < 8; t++) {
            mma16816(acc[t],     ah0, &bh[2*t]);
            mma16816(acc[8 + t], ah1, &bh[2*t]);
        }
    }
}

// 3-stage, single-sync pipelined GEMM mainloop (K advances 64B per iter)
__device__ __forceinline__ void gemm_main(uint32_t sb, const char* gA, const char* gB,
                                          int str, int niter, float (*acc)[4],
                                          int mw, int nw, int lane, int tid)
{
    stageAB(sb, gA, gB, str, tid); CP_COMMIT();
    stageAB(sb + STAGEB, gA + 64, gB + 64, str, tid); CP_COMMIT();
    uint32_t bufs[3] = { sb, sb + STAGEB, sb + 2 * STAGEB };
    for (int kb = 0; kb < niter; kb++) {
        CP_WAIT1();
        __syncthreads();
        if (kb + 2 < niter)
            stageAB(bufs[(kb + 2) % 3], gA + (kb + 2) * 64, gB + (kb + 2) * 64, str, tid);
        CP_COMMIT();
        gemm_step(bufs[kb % 3], acc, mw, nw, lane);
    }
}

// =====================================================================
// Kernel 1: feature generation -> fp16 feature rows (HFMA2 MLP)
// =====================================================================
__global__ void __launch_bounds__(256)
featgen_kernel(const float* __restrict__ cx, const float* __restrict__ xx,
               const float* __restrict__ freq, const float* __restrict__ plr_w,
               const float* __restrict__ plr_b)
{
    __shared__ float    s_x[256 * 33];
    __shared__ float    s_fr[384];
    __shared__ uint32_t s_pw2[512];   // half2(w[2e][f], w[2e+1][f])
    __shared__ uint32_t s_pb2[16];
    const int tid = threadIdx.x;
    const size_t rowBase = (size_t)blockIdx.x * 256;

    for (int i = tid; i < 384; i += 256) s_fr[i] = TWO_PI * freq[i];
    for (int i = tid; i < 512; i += 256) {
        const int e2 = i >> 5, f = i & 31;
        s_pw2[i] = h2pack(plr_w[(2 * e2) * 32 + f], plr_w[(2 * e2 + 1) * 32 + f]);
    }
    if (tid < 16) s_pb2[tid] = h2pack(plr_b[2 * tid], plr_b[2 * tid + 1]);
    for (int i = tid; i < 256 * 32; i += 256) {
        const int r = i >> 5, k = i & 31;
        const size_t gr = rowBase + r;
        float v = 0.f;
        if (gr < NC) v = cx[gr * D_IN + k];
        else if (gr >= NCPAD) v = xx[(gr - NCPAD) * D_IN + k];
        s_x[r * 33 + k] = v;
    }
    __syncthreads();

    const float* xs = s_x + tid * 33;
    __half* dst = g_fb + (rowBase + tid) * KF;
    const __half2 zero2 = __float2half2_rn(0.f);

    for (int n = 0; n < 24; n++) {
        const float v = xs[n];
        __half2 hc[16], hs[16];
#pragma unroll
        for (int f = 0; f < 16; f++) {
            float ss, cc;
            fsincos(s_fr[n * 16 + f] * v, &ss, &cc);
            hs[f] = __float2half2_rn(ss);
            hc[f] = __float2half2_rn(cc);
        }
        uint32_t W[16];
#pragma unroll 4
        for (int e2 = 0; e2 < 16; e2++) {
            __half2 acc2 = *(const __half2*)&s_pb2[e2];
            const __half2* pw = (const __half2*)&s_pw2[e2 * 32];
#pragma unroll
            for (int f = 0; f < 16; f++) {
                acc2 = __hfma2(hc[f], pw[f], acc2);
                acc2 = __hfma2(hs[f], pw[16 + f], acc2);
            }
            const __half2 r2 = __hmax2(acc2, zero2);
            W[e2] = *(const uint32_t*)&r2;
        }
        uint4* dq = (uint4*)((char*)dst + n * 64);
#pragma unroll
        for (int q = 0; q < 4; q++)
            dq[q] = make_uint4(W[4*q], W[4*q+1], W[4*q+2], W[4*q+3]);
    }
#pragma unroll 8
    for (int k = 0; k < 64; k++)   // cat tail 768..775 + zero pad to 832
        dst[768 + k] = __float2half_rn((k < 8) ? xs[24 + k] : 0.f);
}

// =====================================================================
// Kernel 2: pack enc_w -> fp16
// =====================================================================
__global__ void wprep_kernel(const float* __restrict__ enc_w)
{
    const int idx = blockIdx.x * 256 + threadIdx.x;
    if (idx >= DIM * KF) return;
    const int n = idx / KF, k = idx % KF;
    g_wb[(size_t)n * KF + k] = __float2half_rn((k < 776) ? enc_w[n * 776 + k] : 0.f);
}

// =====================================================================
// Kernel 3: encode GEMM (128 rows x 128 cols), fused partial norms
// =====================================================================
__global__ void __launch_bounds__(256, 2)
enc_mma_kernel(const float* __restrict__ enc_b)
{
    extern __shared__ char sm[];
    __shared__ float s_bias[128];
    const uint32_t sb = smem_u32(sm);
    const int tid = threadIdx.x, wid = tid >> 5, lane = tid & 31;
    const int mw = wid >> 1, nw = wid & 1;
    const size_t rowBase = (size_t)blockIdx.x * 128;
    const int colBase = blockIdx.y * 128;
    if (tid < 128) s_bias[tid] = enc_b[colBase + tid];

    const char* gA = (const char*)(g_fb + rowBase * KF);
    const char* gB = (const char*)(g_wb + (size_t)colBase * KF);

    float acc[16][4];
#pragma unroll
    for (int t = 0; t < 16; t++)
#pragma unroll
        for (int u = 0; u < 4; u++) acc[t][u] = 0.f;

    gemm_main(sb, gA, gB, KF * 2, 26, acc, mw, nw, lane, tid);

    // epilogue: bias, fp16 store, quad-reduced partial norms (4 rows/thread)
    const int g = lane >> 2, tig = lane & 3;
    const int nslot = blockIdx.y * 2 + nw;      // 0..7
    float nrm[4] = {0.f, 0.f, 0.f, 0.f};        // rows mw*32 + {g, 8+g, 16+g, 24+g}
#pragma unroll
    for (int t = 0; t < 8; t++) {
        const int col = colBase + nw * 64 + t * 8 + tig * 2;
        const float b0 = s_bias[col - colBase], b1 = s_bias[col - colBase + 1];
        const float v00 = acc[t][0] + b0,     v01 = acc[t][1] + b1;       // row g
        const float v02 = acc[t][2] + b0,     v03 = acc[t][3] + b1;       // row 8+g
        const float v10 = acc[8 + t][0] + b0, v11 = acc[8 + t][1] + b1;   // row 16+g
        const float v12 = acc[8 + t][2] + b0, v13 = acc[8 + t][3] + b1;   // row 24+g
        const size_t r = rowBase + mw * 32 + g;
        *(uint32_t*)(g_emb + r * DIM + col)        = h2pack(v00, v01);
        *(uint32_t*)(g_emb + (r + 8) * DIM + col)  = h2pack(v02, v03);
        *(uint32_t*)(g_emb + (r + 16) * DIM + col) = h2pack(v10, v11);
        *(uint32_t*)(g_emb + (r + 24) * DIM + col) = h2pack(v12, v13);
        nrm[0] = fmaf(v00, v00, fmaf(v01, v01, nrm[0]));
        nrm[1] = fmaf(v02, v02, fmaf(v03, v03, nrm[1]));
        nrm[2] = fmaf(v10, v10, fmaf(v11, v11, nrm[2]));
        nrm[3] = fmaf(v12, v12, fmaf(v13, v13, nrm[3]));
    }
#pragma unroll
    for (int i = 0; i < 4; i++) {
        nrm[i] += __shfl_xor_sync(0xffffffffu, nrm[i], 1);
        nrm[i] += __shfl_xor_sync(0xffffffffu, nrm[i], 2);
    }
    if (tig == 0) {
        const size_t r = rowBase + mw * 32 + g;
        g_nrm8[r * 8 + nslot]        = nrm[0];
        g_nrm8[(r + 8) * 8 + nslot]  = nrm[1];
        g_nrm8[(r + 16) * 8 + nslot] = nrm[2];
        g_nrm8[(r + 24) * 8 + nslot] = nrm[3];
    }
}

// =====================================================================
// Kernel 4: sum partial norms; poison padded candidate rows (exp -> 0)
// =====================================================================
__global__ void __launch_bounds__(256)
norm8_kernel()
{
    const int row = blockIdx.x * 256 + threadIdx.x;
    if (row >= NROWS) return;
    const float4 p0 = *(const float4*)(g_nrm8 + (size_t)row * 8);
    const float4 p1 = *(const float4*)(g_nrm8 + (size_t)row * 8 + 4);
    const float s = ((p0.x + p0.y) + (p0.z + p0.w)) + ((p1.x + p1.y) + (p1.z + p1.w));
    g_nrm[row] = (row < NC || row >= NCPAD) ? s : 1e30f;
}

// =====================================================================
// Kernel 5: NCA GEMM + distance/exp/class partials
// =====================================================================
__global__ void __launch_bounds__(256, 2)
nca_mma_kernel(const int* __restrict__ cy)
{
    extern __shared__ char sm[];
    __shared__ float s_cn[128];
    __shared__ int   s_cy[128];
    const uint32_t sb = smem_u32(sm);
    const int tid = threadIdx.x, wid = tid >> 5, lane = tid & 31;
    const int mw = wid >> 1, nw = wid & 1;
    const int xBase = blockIdx.x * 128;
    const int cBase = blockIdx.y * 128;

    if (tid < 128) {
        const int j = cBase + tid;
        s_cn[tid] = g_nrm[j];                 // 1e30 for padded -> exp == 0
        s_cy[tid] = cy[min(j, NC - 1)];
    }

    const char* gA = (const char*)(g_emb + (size_t)(NCPAD + xBase) * DIM);
    const char* gB = (const char*)(g_emb + (size_t)cBase * DIM);

    float acc[16][4];
#pragma unroll
    for (int t = 0; t < 16; t++)
#pragma unroll
        for (int u = 0; u < 4; u++) acc[t][u] = 0.f;

    gemm_main(sb, gA, gB, DIM * 2, 16, acc, mw, nw, lane, tid);

    // epilogue: two sequential m-frag passes to cap live registers.
    // scores <= 0 -> no online max needed.
    const int g = lane >> 2, tig = lane & 3;
    const int slot = blockIdx.y * 2 + nw;
#pragma unroll
    for (int mf = 0; mf < 2; mf++) {
        const int xr0 = xBase + mw * 32 + mf * 16 + g;
        const float xn0 = g_nrm[NCPAD + xr0];
        const float xn1 = g_nrm[NCPAD + xr0 + 8];
        float n0[D_OUT], n1[D_OUT];
#pragma unroll
        for (int c = 0; c < D_OUT; c++) { n0[c] = 0.f; n1[c] = 0.f; }
#pragma unroll
        for (int t = 0; t < 8; t++) {
            const float* a = acc[mf * 8 + t];
#pragma unroll
            for (int u = 0; u < 2; u++) {
                const int col = nw * 64 + t * 8 + tig * 2 + u;
                const float cn = s_cn[col];
                const int   y  = s_cy[col];
                const float sq0 = fmaxf(xn0 + cn - 2.f * a[u],     1e-12f);
                const float sq1 = fmaxf(xn1 + cn - 2.f * a[2 + u], 1e-12f);
                const float e0 = __expf(-sqrtf(sq0));
                const float e1 = __expf(-sqrtf(sq1));
#pragma unroll
                for (int c = 0; c < D_OUT; c++) {
                    n0[c] += (y == c) ? e0 : 0.f;
                    n1[c] += (y == c) ? e1 : 0.f;
                }
            }
        }
#pragma unroll
        for (int c = 0; c < D_OUT; c++) {
            n0[c] += __shfl_xor_sync(0xffffffffu, n0[c], 1);
            n0[c] += __shfl_xor_sync(0xffffffffu, n0[c], 2);
            n1[c] += __shfl_xor_sync(0xffffffffu, n1[c], 1);
            n1[c] += __shfl_xor_sync(0xffffffffu, n1[c], 2);
        }
        if (tig == 0) {
            float* P0 = g_part + ((size_t)xr0 * NSPLIT2 + slot) * D_OUT;
            float* P1 = g_part + ((size_t)(xr0 + 8) * NSPLIT2 + slot) * D_OUT;
#pragma unroll
            for (int c = 0; c < D_OUT; c++) { P0[c] = n0[c]; P1[c] = n1[c]; }
        }
    }
}

// =====================================================================
// Kernel 6: reduce partials -> log-probs (warp per x row, deterministic)
// =====================================================================
__global__ void __launch_bounds__(256)
finalize_kernel(float* __restrict__ out)
{
    const int w = (blockIdx.x * 256 + threadIdx.x) >> 5;
    const int lane = threadIdx.x & 31;
    if (w >= NX) return;
    const float* P = g_part + (size_t)w * NSPLIT2 * D_OUT;
    float n[D_OUT];
#pragma unroll
    for (int c = 0; c < D_OUT; c++) n[c] = 0.f;
    for (int s = lane; s < NSPLIT2; s += 32) {
        const float* q = P + s * D_OUT;
#pragma unroll
        for (int c = 0; c < D_OUT; c++) n[c] += q[c];
    }
#pragma unroll
    for (int o = 16; o; o >>= 1)
#pragma unroll
        for (int c = 0; c < D_OUT; c++) n[c] += __shfl_xor_sync(0xffffffffu, n[c], o);
    if (lane == 0) {
        float l = 0.f;
#pragma unroll
        for (int c = 0; c < D_OUT; c++) l += n[c];
        const float inv = 1.0f / l;
#pragma unroll
        for (int c = 0; c < D_OUT; c++)
            out[w * D_OUT + c] = logf(n[c] * inv + 1e-7f);
    }
}

// =====================================================================
extern "C" void kernel_launch(void* const* d_in, const int* in_sizes, int n_in,
                              void* d_out, int out_size)
{
    const float* x     = (const float*)d_in[0];
    const float* cx    = (const float*)d_in[1];
    const int*   cy    = (const int*)d_in[2];
    const float* freq  = (const float*)d_in[3];
    const float* plr_w = (const float*)d_in[4];
    const float* plr_b = (const float*)d_in[5];
    const float* enc_w = (const float*)d_in[6];
    const float* enc_b = (const float*)d_in[7];
    float* out = (float*)d_out;

    cudaFuncSetAttribute(enc_mma_kernel, cudaFuncAttributeMaxDynamicSharedMemorySize, DYNSMEM);
    cudaFuncSetAttribute(nca_mma_kernel, cudaFuncAttributeMaxDynamicSharedMemorySize, DYNSMEM);

    featgen_kernel<<<NROWS / 256, 256>>>(cx, x, freq, plr_w, plr_b);
    wprep_kernel<<<(DIM * KF + 255) / 256, 256>>>(enc_w);
    enc_mma_kernel<<<dim3(NROWS / 128, DIM / 128), 256, DYNSMEM>>>(enc_b);
    norm8_kernel<<<(NROWS + 255) / 256, 256>>>();
    nca_mma_kernel<<<dim3(NX / 128, NCPAD / 128), 256, DYNSMEM>>>(cy);
    finalize_kernel<<<(NX * 32) / 256, 256>>>(out);
}